// round 12
// baseline (speedup 1.0000x reference)
#include <cuda_runtime.h>
#include <math.h>

#define H_    128
#define B_    4096
#define KIN_  8
#define KOUT_ 4
#define PRE_  64
#define FWD_  128
#define BB_   16
#define NBLK_ (B_/BB_)

typedef unsigned long long u64;

__device__ __align__(16) float g_Wrz[256*64*4];   // ODE r/z:  [k][jp]{r0,r1,z0,z1}
__device__ __align__(16) float g_Wn [256*64*2];   // ODE n:    [k][j]
__device__ __align__(16) float g_Erz[140*64*4];   // enc r/z
__device__ __align__(16) float g_En [140*64*2];   // enc n
__device__ __align__(16) float g_WeT[KIN_*H_];
__device__ __align__(16) float g_W1T[H_*256];
__device__ float g_umid[(size_t)FWD_*B_*KIN_];
__device__ float g_dp  [(size_t)FWD_*B_*KIN_];

__global__ void prep_weights(const float* __restrict__ W_ih, const float* __restrict__ W_hh,
                             const float* __restrict__ W_e,  const float* __restrict__ Wc_ih,
                             const float* __restrict__ Wc_hh,const float* __restrict__ W1){
  int i = blockIdx.x*blockDim.x + threadIdx.x;
  if (i < 256*256){
    int k=i>>8, rem=i&255, jp=rem>>2, q=rem&3, g=q>>1, j=jp*2+(q&1), c=g*128+j;
    g_Wrz[i] = (k<128)? Wc_hh[c*128+k] : Wc_ih[c*128+(k-128)];
  }
  if (i < 256*128){
    int k=i>>7, j=i&127, c=256+j;
    g_Wn[i] = (k<128)? Wc_hh[c*128+k] : Wc_ih[c*128+(k-128)];
  }
  if (i < 140*256){
    int k=i>>8, rem=i&255, jp=rem>>2, q=rem&3, g=q>>1, j=jp*2+(q&1), c=g*128+j;
    g_Erz[i] = (k<128)? W_hh[c*128+k] : W_ih[c*12+(k-128)];
  }
  if (i < 140*128){
    int k=i>>7, j=i&127, c=256+j;
    g_En[i] = (k<128)? W_hh[c*128+k] : W_ih[c*12+(k-128)];
  }
  if (i < KIN_*H_){ int c=i>>7, j=i&127; g_WeT[i] = W_e[j*KIN_+c]; }
  if (i < H_*256) { int k=i>>8, j=i&255; g_W1T[i] = W1[j*H_+k]; }
}

__global__ void spline_kernel(const float* __restrict__ pre_x, const float* __restrict__ fwd_x){
  __shared__ float cp[128];
  if (threadIdx.x == 0){ float c=0.f; for (int i=1;i<128;i++){ c=1.f/(4.f-c); cp[i]=c; } }
  __syncthreads();
  int idx = blockIdx.x*blockDim.x + threadIdx.x;
  if (idx >= B_*KIN_) return;
  const float hs2 = 0.01f;
#define YS(t) ((t)==0 ? pre_x[(size_t)(PRE_-1)*B_*KIN_ + idx] : fwd_x[(size_t)((t)-1)*B_*KIN_ + idx])
  float y0 = YS(0), y1 = YS(1), dprev = 0.f;
  for (int i=1;i<=127;i++){
    float y2 = YS(i+1);
    float rhs = 6.f*(y0 - 2.f*y1 + y2)/hs2;
    float d = (rhs - dprev)*cp[i];
    g_dp[(size_t)i*B_*KIN_ + idx] = d;
    dprev = d; y0 = y1; y1 = y2;
  }
  float Mn = 0.f;
  for (int i=127;i>=1;i--){
    float Mi = g_dp[(size_t)i*B_*KIN_ + idx] - cp[i]*Mn;
    g_umid[(size_t)i*B_*KIN_ + idx] = 0.5f*(YS(i)+YS(i+1)) - (Mi+Mn)*(hs2/16.f);
    Mn = Mi;
  }
  g_umid[idx] = 0.5f*(YS(0)+YS(1)) - Mn*(hs2/16.f);
#undef YS
}

__device__ __forceinline__ float sig_(float x){ return __fdividef(1.f, 1.f + __expf(-x)); }
__device__ __forceinline__ float tanh_(float x){ return 1.f - __fdividef(2.f, __expf(2.f*x) + 1.f); }

__device__ __forceinline__ void upk2(float& lo, float& hi, u64 v){
  asm("mov.b64 {%0, %1}, %2;" : "=f"(lo), "=f"(hi) : "l"(v));
}
__device__ __forceinline__ void fma2(u64& d, u64 a, u64 b){
  asm("fma.rn.f32x2 %0, %1, %2, %3;" : "=l"(d) : "l"(a), "l"(b), "l"(d));
}

// O is duplicated layout: row k = 32 floats = 16 pre-packed (v,v) u64s
__device__ __forceinline__ void gemm2(const float* __restrict__ Wrz, const float* __restrict__ Wn,
                                      const ulonglong2* __restrict__ O2, int jg, int bg, int k0, int k1,
                                      u64 aR[4], u64 aZ[4], u64 aN[4]){
  const ulonglong2* Wp = (const ulonglong2*)Wrz;
  const u64* Np = (const u64*)Wn;
#pragma unroll 4
  for (int k=k0;k<k1;k++){
    ulonglong2 oa = O2[k*8 + bg*2], ob = O2[k*8 + bg*2 + 1];
    ulonglong2 wrz = __ldg(Wp + k*64 + jg);
    u64 wn = __ldg(Np + k*64 + jg);
    u64 o[4] = {oa.x, oa.y, ob.x, ob.y};
#pragma unroll
    for (int bb=0;bb<4;bb++){
      fma2(aR[bb], wrz.x, o[bb]);
      fma2(aZ[bb], wrz.y, o[bb]);
      fma2(aN[bb], wn,    o[bb]);
    }
  }
}

__device__ __forceinline__ void gru_epi(const u64 aR[4], const u64 aZ[4],
                                        const u64 aNh[4], const u64 aNi[4],
                                        const float bR[2], const float bZ[2],
                                        const float bI[2], const float bH[2],
                                        const float hin[2][4], float outv[2][4]){
#pragma unroll
  for (int bb=0;bb<4;bb++){
    float r0,r1,z0,z1,h0,h1,i0,i1;
    upk2(r0,r1,aR[bb]); upk2(z0,z1,aZ[bb]);
    upk2(h0,h1,aNh[bb]); upk2(i0,i1,aNi[bb]);
    float r = sig_(r0 + bR[0]), z = sig_(z0 + bZ[0]);
    float n = tanh_(i0 + bI[0] + r*(h0 + bH[0]));
    outv[0][bb] = (1.f - z)*n + z*hin[0][bb];
    r = sig_(r1 + bR[1]); z = sig_(z1 + bZ[1]);
    n = tanh_(i1 + bI[1] + r*(h1 + bH[1]));
    outv[1][bb] = (1.f - z)*n + z*hin[1][bb];
  }
}

__device__ __forceinline__ void save_part(float* P, int tid, const u64 aR[4], const u64 aZ[4], const u64 aN[4]){
  ulonglong2* Pp = (ulonglong2*)(P + tid*32);
  Pp[0]=make_ulonglong2(aR[0],aR[1]); Pp[1]=make_ulonglong2(aR[2],aR[3]);
  Pp[2]=make_ulonglong2(aZ[0],aZ[1]); Pp[3]=make_ulonglong2(aZ[2],aZ[3]);
  Pp[4]=make_ulonglong2(aN[0],aN[1]); Pp[5]=make_ulonglong2(aN[2],aN[3]);
}
__device__ __forceinline__ void load_part(const float* P, int tid, u64 aR[4], u64 aZ[4], u64 aN[4]){
  const ulonglong2* Pp = (const ulonglong2*)(P + tid*32);
  ulonglong2 v;
  v=Pp[0]; aR[0]=v.x; aR[1]=v.y;  v=Pp[1]; aR[2]=v.x; aR[3]=v.y;
  v=Pp[2]; aZ[0]=v.x; aZ[1]=v.y;  v=Pp[3]; aZ[2]=v.x; aZ[3]=v.y;
  v=Pp[4]; aN[0]=v.x; aN[1]=v.y;  v=Pp[5]; aN[2]=v.x; aN[3]=v.y;
}

__device__ __forceinline__ void gru_full(const ulonglong2* O2, float* P, int tid, int jg, int bg,
                                         const float bR[2], const float bZ[2],
                                         const float bI[2], const float bH[2],
                                         const float hin[2][4], float outv[2][4]){
  u64 aR[4]={}, aZ[4]={}, aNh[4]={}, aNi[4]={};
  gemm2(g_Wrz, g_Wn, O2, jg, bg, 128, 256, aR, aZ, aNi);
  save_part(P, tid, aR, aZ, aNi);
  gemm2(g_Wrz, g_Wn, O2, jg, bg, 0, 128, aR, aZ, aNh);
  gru_epi(aR, aZ, aNh, aNi, bR, bZ, bI, bH, hin, outv);
}
__device__ __forceinline__ void gru_half(const ulonglong2* O2, const float* P, int tid, int jg, int bg,
                                         const float bR[2], const float bZ[2],
                                         const float bI[2], const float bH[2],
                                         const float hin[2][4], float outv[2][4]){
  u64 aR[4], aZ[4], aNh[4]={}, aNi[4];
  load_part(P, tid, aR, aZ, aNi);
  gemm2(g_Wrz, g_Wn, O2, jg, bg, 0, 128, aR, aZ, aNh);
  gru_epi(aR, aZ, aNh, aNi, bR, bZ, bI, bH, hin, outv);
}
__device__ __forceinline__ void gru_enc(const ulonglong2* O2, int jg, int bg,
                                        const float bR[2], const float bZ[2],
                                        const float bI[2], const float bH[2],
                                        const float hin[2][4], float outv[2][4]){
  u64 aR[4]={}, aZ[4]={}, aNh[4]={}, aNi[4]={};
  gemm2(g_Erz, g_En, O2, jg, bg, 0,   128, aR, aZ, aNh);
  gemm2(g_Erz, g_En, O2, jg, bg, 128, 140, aR, aZ, aNi);
  gru_epi(aR, aZ, aNh, aNi, bR, bZ, bI, bH, hin, outv);
}

// write 2 j-rows x 4 dup batch values into dup layout
__device__ __forceinline__ void store_dup(float* O, int row0, int bg, const float v[2][4]){
  float4* O4 = (float4*)O;   // row = 8 float4
#pragma unroll
  for (int jj=0;jj<2;jj++){
    O4[(row0+jj)*8 + bg*2]     = make_float4(v[jj][0],v[jj][0],v[jj][1],v[jj][1]);
    O4[(row0+jj)*8 + bg*2 + 1] = make_float4(v[jj][2],v[jj][2],v[jj][3],v[jj][3]);
  }
}

__device__ __forceinline__ void compute_x(const float* __restrict__ usrc, float* __restrict__ O,
                                          int jg, int bg, int b0, const float bev[2]){
  float uv[4][8];
#pragma unroll
  for (int bb=0;bb<4;bb++){
    const float4* p = (const float4*)(usrc + (size_t)(b0 + bg*4 + bb)*KIN_);
    float4 u0 = __ldg(p), u1 = __ldg(p+1);
    uv[bb][0]=u0.x; uv[bb][1]=u0.y; uv[bb][2]=u0.z; uv[bb][3]=u0.w;
    uv[bb][4]=u1.x; uv[bb][5]=u1.y; uv[bb][6]=u1.z; uv[bb][7]=u1.w;
  }
  float acc[2][4];
#pragma unroll
  for (int jj=0;jj<2;jj++)
#pragma unroll
    for (int bb=0;bb<4;bb++) acc[jj][bb]=bev[jj];
  const float2* Wv = (const float2*)g_WeT;
#pragma unroll
  for (int c=0;c<8;c++){
    float2 w = __ldg(Wv + c*64 + jg);
#pragma unroll
    for (int bb=0;bb<4;bb++){
      acc[0][bb] = fmaf(w.x, uv[bb][c], acc[0][bb]);
      acc[1][bb] = fmaf(w.y, uv[bb][c], acc[1][bb]);
    }
  }
  float xv[2][4];
#pragma unroll
  for (int jj=0;jj<2;jj++)
#pragma unroll
    for (int bb=0;bb<4;bb++) xv[jj][bb] = tanh_(acc[jj][bb]);
  store_dup(O, 128 + jg*2, bg, xv);
}

__global__ __launch_bounds__(256,2)
void ode_kernel(const float* __restrict__ pre_x, const float* __restrict__ pre_y,
                const float* __restrict__ fwd_x,
                const float* __restrict__ b_ih,  const float* __restrict__ b_hh,
                const float* __restrict__ b_e,
                const float* __restrict__ bc_ih, const float* __restrict__ bc_hh,
                const float* __restrict__ W2, float* __restrict__ out){
  extern __shared__ float sm[];
  float* O = sm;               // dup layout: 256 rows x 32 floats = 8192
  float* Z = sm + 8192;        // 256 x 17 padded = 4352
  float* P = sm + 12544;       // 256 threads x 32 floats = 8192
  const ulonglong2* O2 = (const ulonglong2*)O;
  const int tid = threadIdx.x, jg = tid & 63, bg = tid >> 6;
  const int b0 = blockIdx.x * BB_;
  const int j0 = jg*2;

  float beR[2],beZ[2],beI[2],beH[2],bcR[2],bcZ[2],bcI[2],bcH[2],bev[2];
#pragma unroll
  for (int jj=0;jj<2;jj++){
    int j = j0 + jj;
    beR[jj]=b_ih[j]+b_hh[j];           beZ[jj]=b_ih[128+j]+b_hh[128+j];
    beI[jj]=b_ih[256+j];               beH[jj]=b_hh[256+j];
    bcR[jj]=bc_ih[j]+bc_hh[j];         bcZ[jj]=bc_ih[128+j]+bc_hh[128+j];
    bcI[jj]=bc_ih[256+j];              bcH[jj]=bc_hh[256+j];
    bev[jj]=b_e[j];
  }

  // ---- encoder ----
  float y[2][4];
#pragma unroll
  for (int jj=0;jj<2;jj++)
#pragma unroll
    for (int bb=0;bb<4;bb++) y[jj][bb]=0.f;
  store_dup(O, j0, bg, y);
  for (int t=0;t<PRE_;t++){
    if (tid < 192){
      int rr = tid>>4, bq = tid&15;
      int b = b0 + bq;
      float v = (rr<8) ? pre_x[((size_t)t*B_+b)*KIN_+rr] : pre_y[((size_t)t*B_+b)*KOUT_+(rr-8)];
      ((float2*)O)[(128+rr)*16 + bq] = make_float2(v,v);
    }
    __syncthreads();
    float hn[2][4];
    gru_enc(O2, jg, bg, beR,beZ,beI,beH, y, hn);
    __syncthreads();
    store_dup(O, j0, bg, hn);
#pragma unroll
    for (int jj=0;jj<2;jj++)
#pragma unroll
      for (int bb=0;bb<4;bb++) y[jj][bb]=hn[jj][bb];
  }
  compute_x(pre_x + (size_t)(PRE_-1)*B_*KIN_, O, jg, bg, b0, bev);
  __syncthreads();
  {
    u64 aR[4]={}, aZ[4]={}, aNi[4]={};
    gemm2(g_Wrz, g_Wn, O2, jg, bg, 128, 256, aR, aZ, aNi);
    save_part(P, tid, aR, aZ, aNi);
  }

  const float C16 = 0.1f/6.f, C13 = 0.1f/3.f;
  const int jp = tid & 127, half = tid >> 7;   // head mapping
  for (int i=0;i<FWD_;i++){
    float cell[2][4], acc[2][4], tc[2][4], f;
    // eval1: half (P = knot i)
    gru_half(O2, P, tid, jg, bg, bcR,bcZ,bcI,bcH, y, cell);
    __syncthreads();
#pragma unroll
    for (int jj=0;jj<2;jj++)
#pragma unroll
      for (int bb=0;bb<4;bb++){
        f = (cell[jj][bb]-y[jj][bb])*10.f;
        acc[jj][bb] = y[jj][bb] + C16*f;  tc[jj][bb] = y[jj][bb] + 0.05f*f;
      }
    store_dup(O, j0, bg, tc);
    compute_x(g_umid + (size_t)i*B_*KIN_, O, jg, bg, b0, bev);
    __syncthreads();
    // eval2: full (captures P = mid)
    gru_full(O2, P, tid, jg, bg, bcR,bcZ,bcI,bcH, tc, cell);
    __syncthreads();
#pragma unroll
    for (int jj=0;jj<2;jj++)
#pragma unroll
      for (int bb=0;bb<4;bb++){
        f = (cell[jj][bb]-tc[jj][bb])*10.f;
        acc[jj][bb] += C13*f;  tc[jj][bb] = y[jj][bb] + 0.05f*f;
      }
    store_dup(O, j0, bg, tc);
    __syncthreads();
    // eval3: half (P = mid)
    gru_half(O2, P, tid, jg, bg, bcR,bcZ,bcI,bcH, tc, cell);
    __syncthreads();
#pragma unroll
    for (int jj=0;jj<2;jj++)
#pragma unroll
      for (int bb=0;bb<4;bb++){
        f = (cell[jj][bb]-tc[jj][bb])*10.f;
        acc[jj][bb] += C13*f;  tc[jj][bb] = y[jj][bb] + 0.1f*f;
      }
    store_dup(O, j0, bg, tc);
    compute_x(fwd_x + (size_t)i*B_*KIN_, O, jg, bg, b0, bev);
    __syncthreads();
    // eval4: full (captures P = knot i+1)
    gru_full(O2, P, tid, jg, bg, bcR,bcZ,bcI,bcH, tc, cell);
    __syncthreads();
#pragma unroll
    for (int jj=0;jj<2;jj++)
#pragma unroll
      for (int bb=0;bb<4;bb++){
        f = (cell[jj][bb]-tc[jj][bb])*10.f;
        y[jj][bb] = acc[jj][bb] + C16*f;
      }
    store_dup(O, j0, bg, y);
    __syncthreads();
    // ---- head ----
    {
      u64 ha2[8] = {};
      const u64* W1p = (const u64*)g_W1T;
      for (int k=0;k<128;k++){
        u64 w2 = __ldg(W1p + k*128 + jp);
        const ulonglong2* orow = (const ulonglong2*)(O + k*32) + half*4;
        ulonglong2 a=orow[0], b2=orow[1], c2=orow[2], d2=orow[3];
        fma2(ha2[0],w2,a.x);  fma2(ha2[1],w2,a.y);
        fma2(ha2[2],w2,b2.x); fma2(ha2[3],w2,b2.y);
        fma2(ha2[4],w2,c2.x); fma2(ha2[5],w2,c2.y);
        fma2(ha2[6],w2,d2.x); fma2(ha2[7],w2,d2.y);
      }
#pragma unroll
      for (int q=0;q<8;q++){
        float v0,v1; upk2(v0,v1,ha2[q]);
        int b = half*8 + q;
        Z[(jp*2+0)*17 + b] = tanh_(v0);
        Z[(jp*2+1)*17 + b] = tanh_(v1);
      }
      __syncthreads();
      if (tid < 64){
        int c = tid>>4, b = tid&15;
        float s0=0.f,s1=0.f,s2=0.f,s3=0.f;
        for (int k=0;k<256;k+=4){
          s0 = fmaf(__ldg(W2 + c*256 + k+0), Z[(k+0)*17+b], s0);
          s1 = fmaf(__ldg(W2 + c*256 + k+1), Z[(k+1)*17+b], s1);
          s2 = fmaf(__ldg(W2 + c*256 + k+2), Z[(k+2)*17+b], s2);
          s3 = fmaf(__ldg(W2 + c*256 + k+3), Z[(k+3)*17+b], s3);
        }
        out[((size_t)i*B_ + b0 + b)*KOUT_ + c] = (s0+s1)+(s2+s3);
      }
      __syncthreads();
    }
  }
}

extern "C" void kernel_launch(void* const* d_in, const int* in_sizes, int n_in,
                              void* d_out, int out_size){
  const float* pre_x = (const float*)d_in[0];
  const float* pre_y = (const float*)d_in[1];
  const float* fwd_x = (const float*)d_in[2];
  const float* W_ih  = (const float*)d_in[3];
  const float* W_hh  = (const float*)d_in[4];
  const float* b_ih  = (const float*)d_in[5];
  const float* b_hh  = (const float*)d_in[6];
  const float* W_e   = (const float*)d_in[7];
  const float* b_e   = (const float*)d_in[8];
  const float* Wc_ih = (const float*)d_in[9];
  const float* Wc_hh = (const float*)d_in[10];
  const float* bc_ih = (const float*)d_in[11];
  const float* bc_hh = (const float*)d_in[12];
  const float* W1    = (const float*)d_in[13];
  const float* W2    = (const float*)d_in[14];
  float* out = (float*)d_out;

  cudaFuncSetAttribute(ode_kernel, cudaFuncAttributeMaxDynamicSharedMemorySize, 82944);
  prep_weights<<<256,256>>>(W_ih, W_hh, W_e, Wc_ih, Wc_hh, W1);
  spline_kernel<<<(B_*KIN_+255)/256,256>>>(pre_x, fwd_x);
  ode_kernel<<<NBLK_,256,82944>>>(pre_x, pre_y, fwd_x, b_ih, b_hh, b_e,
                                  bc_ih, bc_hh, W2, out);
}

// round 14
// speedup vs baseline: 1.2822x; 1.2822x over previous
#include <cuda_runtime.h>
#include <cuda_bf16.h>
#include <math.h>

#define H_    128
#define B_    4096
#define KIN_  8
#define KOUT_ 4
#define PRE_  64
#define FWD_  128
#define BB_   16
#define NBLK_ (B_/BB_)

typedef unsigned long long u64;

__device__ __align__(16) float g_WOD [256*384];           // ODE fp32 (input half k>=128 used)
__device__ __align__(16) __nv_bfloat16 g_WHh[128*384];    // ODE hidden half, bf16
__device__ __align__(16) float g_WENC[140*384];           // encoder fp32
__device__ __align__(16) float g_WeT[KIN_*H_];
__device__ __align__(16) float g_W1T[H_*256];
__device__ float g_umid[(size_t)FWD_*B_*KIN_];
__device__ float g_dp  [(size_t)FWD_*B_*KIN_];

// merged prep + spline (keeps launch count at 2 per call so ncu -s5 hits ode_kernel)
__global__ void prep_all(const float* __restrict__ W_ih, const float* __restrict__ W_hh,
                         const float* __restrict__ W_e,  const float* __restrict__ Wc_ih,
                         const float* __restrict__ Wc_hh,const float* __restrict__ W1,
                         const float* __restrict__ pre_x,const float* __restrict__ fwd_x){
  __shared__ float cp[128];
  if (blockIdx.x < 384){
    int i = blockIdx.x*256 + threadIdx.x;
    if (i < 256*384){ int k=i/384, c=i%384; g_WOD[i] = (k<128)? Wc_hh[c*128+k] : Wc_ih[c*128+(k-128)]; }
    if (i < 128*384){ int k=i/384, c=i%384; g_WHh[i] = __float2bfloat16(Wc_hh[c*128+k]); }
    if (i < 140*384){ int k=i/384, c=i%384; g_WENC[i] = (k<128)? W_hh[c*128+k] : W_ih[c*12+(k-128)]; }
    if (i < KIN_*H_){ int c=i>>7, j=i&127; g_WeT[i] = W_e[j*KIN_+c]; }
    if (i < H_*256) { int k=i>>8, j=i&255; g_W1T[i] = W1[j*H_+k]; }
  } else {
    if (threadIdx.x == 0){ float c=0.f; for (int i=1;i<128;i++){ c=1.f/(4.f-c); cp[i]=c; } }
    __syncthreads();
    int idx = (blockIdx.x-384)*256 + threadIdx.x;
    if (idx >= B_*KIN_) return;
    const float hs2 = 0.01f;
#define YS(t) ((t)==0 ? pre_x[(size_t)(PRE_-1)*B_*KIN_ + idx] : fwd_x[(size_t)((t)-1)*B_*KIN_ + idx])
    float y0 = YS(0), y1 = YS(1), dprev = 0.f;
    for (int i=1;i<=127;i++){
      float y2 = YS(i+1);
      float rhs = 6.f*(y0 - 2.f*y1 + y2)/hs2;
      float d = (rhs - dprev)*cp[i];
      g_dp[(size_t)i*B_*KIN_ + idx] = d;
      dprev = d; y0 = y1; y1 = y2;
    }
    float Mn = 0.f;
    for (int i=127;i>=1;i--){
      float Mi = g_dp[(size_t)i*B_*KIN_ + idx] - cp[i]*Mn;
      g_umid[(size_t)i*B_*KIN_ + idx] = 0.5f*(YS(i)+YS(i+1)) - (Mi+Mn)*(hs2/16.f);
      Mn = Mi;
    }
    g_umid[idx] = 0.5f*(YS(0)+YS(1)) - Mn*(hs2/16.f);
#undef YS
  }
}

__device__ __forceinline__ float sig_(float x){ return __fdividef(1.f, 1.f + __expf(-x)); }
__device__ __forceinline__ float tanh_(float x){ return 1.f - __fdividef(2.f, __expf(2.f*x) + 1.f); }

__device__ __forceinline__ u64 pk2(float v){
  u64 r; asm("mov.b64 %0, {%1, %1};" : "=l"(r) : "f"(v)); return r;
}
__device__ __forceinline__ void upk2(float& lo, float& hi, u64 v){
  asm("mov.b64 {%0, %1}, %2;" : "=f"(lo), "=f"(hi) : "l"(v));
}
__device__ __forceinline__ void fma2(u64& d, u64 a, u64 b){
  asm("fma.rn.f32x2 %0, %1, %2, %3;" : "=l"(d) : "l"(a), "l"(b), "l"(d));
}
__device__ __forceinline__ u64 bf2f2(unsigned v){
  unsigned lo = v << 16, hi = v & 0xFFFF0000u;
  u64 r; asm("mov.b64 %0, {%1, %2};" : "=l"(r) : "r"(lo), "r"(hi));
  return r;
}

// fp32-weight gemm over k in [k0,k1)
__device__ __forceinline__ void gemm2f(const float* __restrict__ Wg, const float4* __restrict__ O4,
                                       int jg, int bg, int k0, int k1,
                                       u64 aR[4], u64 aZ[4], u64 aN[4]){
  const u64* W8 = (const u64*)Wg;
#pragma unroll 4
  for (int k=k0;k<k1;k++){
    float4 o = O4[k*4 + bg];
    u64 wr = __ldg(W8 + (k*3+0)*64 + jg);
    u64 wz = __ldg(W8 + (k*3+1)*64 + jg);
    u64 wn = __ldg(W8 + (k*3+2)*64 + jg);
    u64 ob[4] = {pk2(o.x), pk2(o.y), pk2(o.z), pk2(o.w)};
#pragma unroll
    for (int bb=0;bb<4;bb++){
      fma2(aR[bb], wr, ob[bb]);
      fma2(aZ[bb], wz, ob[bb]);
      fma2(aN[bb], wn, ob[bb]);
    }
  }
}
// bf16-weight gemm, hidden half k in [0,128)
__device__ __forceinline__ void gemm2h(const float4* __restrict__ O4, int jg, int bg,
                                       u64 aR[4], u64 aZ[4], u64 aN[4]){
  const unsigned* Wp = (const unsigned*)g_WHh;
#pragma unroll 4
  for (int k=0;k<128;k++){
    float4 o = O4[k*4 + bg];
    unsigned hr = __ldg(Wp + (k*3+0)*64 + jg);
    unsigned hz = __ldg(Wp + (k*3+1)*64 + jg);
    unsigned hn = __ldg(Wp + (k*3+2)*64 + jg);
    u64 wr = bf2f2(hr), wz = bf2f2(hz), wn = bf2f2(hn);
    u64 ob[4] = {pk2(o.x), pk2(o.y), pk2(o.z), pk2(o.w)};
#pragma unroll
    for (int bb=0;bb<4;bb++){
      fma2(aR[bb], wr, ob[bb]);
      fma2(aZ[bb], wz, ob[bb]);
      fma2(aN[bb], wn, ob[bb]);
    }
  }
}

__device__ __forceinline__ void gru_epi(const u64 aR[4], const u64 aZ[4],
                                        const u64 aNh[4], const u64 aNi[4],
                                        const float bR[2], const float bZ[2],
                                        const float bI[2], const float bH[2],
                                        const float hin[2][4], float outv[2][4]){
#pragma unroll
  for (int bb=0;bb<4;bb++){
    float r0,r1,z0,z1,h0,h1,i0,i1;
    upk2(r0,r1,aR[bb]); upk2(z0,z1,aZ[bb]);
    upk2(h0,h1,aNh[bb]); upk2(i0,i1,aNi[bb]);
    float r = sig_(r0 + bR[0]), z = sig_(z0 + bZ[0]);
    float n = tanh_(i0 + bI[0] + r*(h0 + bH[0]));
    outv[0][bb] = (1.f - z)*n + z*hin[0][bb];
    r = sig_(r1 + bR[1]); z = sig_(z1 + bZ[1]);
    n = tanh_(i1 + bI[1] + r*(h1 + bH[1]));
    outv[1][bb] = (1.f - z)*n + z*hin[1][bb];
  }
}

// partials: transposed slot layout [12][256] u64 -> 24KB, conflict-free
__device__ __forceinline__ void save_part(u64* P, int tid, const u64 aR[4], const u64 aZ[4], const u64 aN[4]){
#pragma unroll
  for (int s=0;s<4;s++){ P[s*256+tid]=aR[s]; P[(4+s)*256+tid]=aZ[s]; P[(8+s)*256+tid]=aN[s]; }
}
__device__ __forceinline__ void load_part(const u64* P, int tid, u64 aR[4], u64 aZ[4], u64 aN[4]){
#pragma unroll
  for (int s=0;s<4;s++){ aR[s]=P[s*256+tid]; aZ[s]=P[(4+s)*256+tid]; aN[s]=P[(8+s)*256+tid]; }
}

__device__ __forceinline__ void gru_full(const float4* O4, u64* P, int tid, int jg, int bg,
                                         const float bR[2], const float bZ[2],
                                         const float bI[2], const float bH[2],
                                         const float hin[2][4], float outv[2][4]){
  u64 aR[4]={}, aZ[4]={}, aNh[4]={}, aNi[4]={};
  gemm2f(g_WOD, O4, jg, bg, 128, 256, aR, aZ, aNi);
  save_part(P, tid, aR, aZ, aNi);
  gemm2h(O4, jg, bg, aR, aZ, aNh);
  gru_epi(aR, aZ, aNh, aNi, bR, bZ, bI, bH, hin, outv);
}
__device__ __forceinline__ void gru_half(const float4* O4, const u64* P, int tid, int jg, int bg,
                                         const float bR[2], const float bZ[2],
                                         const float bI[2], const float bH[2],
                                         const float hin[2][4], float outv[2][4]){
  u64 aR[4], aZ[4], aNh[4]={}, aNi[4];
  load_part(P, tid, aR, aZ, aNi);
  gemm2h(O4, jg, bg, aR, aZ, aNh);
  gru_epi(aR, aZ, aNh, aNi, bR, bZ, bI, bH, hin, outv);
}
__device__ __forceinline__ void gru_enc(const float4* O4, int jg, int bg,
                                        const float bR[2], const float bZ[2],
                                        const float bI[2], const float bH[2],
                                        const float hin[2][4], float outv[2][4]){
  u64 aR[4]={}, aZ[4]={}, aNh[4]={}, aNi[4]={};
  gemm2f(g_WENC, O4, jg, bg, 0,   128, aR, aZ, aNh);
  gemm2f(g_WENC, O4, jg, bg, 128, 140, aR, aZ, aNi);
  gru_epi(aR, aZ, aNh, aNi, bR, bZ, bI, bH, hin, outv);
}

__device__ __forceinline__ void compute_x(const float* __restrict__ usrc, float* __restrict__ O,
                                          int jg, int bg, int b0, const float bev[2]){
  float uv[4][8];
#pragma unroll
  for (int bb=0;bb<4;bb++){
    const float4* p = (const float4*)(usrc + (size_t)(b0 + bg*4 + bb)*KIN_);
    float4 u0 = __ldg(p), u1 = __ldg(p+1);
    uv[bb][0]=u0.x; uv[bb][1]=u0.y; uv[bb][2]=u0.z; uv[bb][3]=u0.w;
    uv[bb][4]=u1.x; uv[bb][5]=u1.y; uv[bb][6]=u1.z; uv[bb][7]=u1.w;
  }
  float acc[2][4];
#pragma unroll
  for (int jj=0;jj<2;jj++)
#pragma unroll
    for (int bb=0;bb<4;bb++) acc[jj][bb]=bev[jj];
  const float2* Wv = (const float2*)g_WeT;
#pragma unroll
  for (int c=0;c<8;c++){
    float2 w = __ldg(Wv + c*64 + jg);
#pragma unroll
    for (int bb=0;bb<4;bb++){
      acc[0][bb] = fmaf(w.x, uv[bb][c], acc[0][bb]);
      acc[1][bb] = fmaf(w.y, uv[bb][c], acc[1][bb]);
    }
  }
  float4* O4 = (float4*)O;
#pragma unroll
  for (int jj=0;jj<2;jj++)
    O4[(128 + jg*2 + jj)*4 + bg] =
      make_float4(tanh_(acc[jj][0]),tanh_(acc[jj][1]),tanh_(acc[jj][2]),tanh_(acc[jj][3]));
}

__global__ __launch_bounds__(256,2)
void ode_kernel(const float* __restrict__ pre_x, const float* __restrict__ pre_y,
                const float* __restrict__ fwd_x,
                const float* __restrict__ b_ih,  const float* __restrict__ b_hh,
                const float* __restrict__ b_e,
                const float* __restrict__ bc_ih, const float* __restrict__ bc_hh,
                const float* __restrict__ W2, float* __restrict__ out){
  extern __shared__ float sm[];
  float* O = sm;                    // [256][16] = 16KB
  float* Z = sm + 4096;             // 16KB
  u64*   P = (u64*)(sm + 8192);     // [12][256] u64 = 24KB
  float4* O4 = (float4*)O;
  const int tid = threadIdx.x, jg = tid & 63, bg = tid >> 6;
  const int b0 = blockIdx.x * BB_;
  const int j0 = jg*2;

  float beR[2],beZ[2],beI[2],beH[2],bcR[2],bcZ[2],bcI[2],bcH[2],bev[2];
#pragma unroll
  for (int jj=0;jj<2;jj++){
    int j = j0 + jj;
    beR[jj]=b_ih[j]+b_hh[j];           beZ[jj]=b_ih[128+j]+b_hh[128+j];
    beI[jj]=b_ih[256+j];               beH[jj]=b_hh[256+j];
    bcR[jj]=bc_ih[j]+bc_hh[j];         bcZ[jj]=bc_ih[128+j]+bc_hh[128+j];
    bcI[jj]=bc_ih[256+j];              bcH[jj]=bc_hh[256+j];
    bev[jj]=b_e[j];
  }

  // ---- encoder ----
  float y[2][4];
#pragma unroll
  for (int jj=0;jj<2;jj++){
#pragma unroll
    for (int bb=0;bb<4;bb++) y[jj][bb]=0.f;
    O4[(j0+jj)*4 + bg] = make_float4(0.f,0.f,0.f,0.f);
  }
  for (int t=0;t<PRE_;t++){
    if (tid < 192){
      int rr = tid>>4, bq = tid&15;
      int b = b0 + bq;
      float v = (rr<8) ? pre_x[((size_t)t*B_+b)*KIN_+rr] : pre_y[((size_t)t*B_+b)*KOUT_+(rr-8)];
      O[(128+rr)*16 + bq] = v;
    }
    __syncthreads();
    float hn[2][4];
    gru_enc(O4, jg, bg, beR,beZ,beI,beH, y, hn);
    __syncthreads();
#pragma unroll
    for (int jj=0;jj<2;jj++){
      O4[(j0+jj)*4+bg] = make_float4(hn[jj][0],hn[jj][1],hn[jj][2],hn[jj][3]);
#pragma unroll
      for (int bb=0;bb<4;bb++) y[jj][bb]=hn[jj][bb];
    }
  }
  compute_x(pre_x + (size_t)(PRE_-1)*B_*KIN_, O, jg, bg, b0, bev);
  __syncthreads();
  {
    u64 aR[4]={}, aZ[4]={}, aNi[4]={};
    gemm2f(g_WOD, O4, jg, bg, 128, 256, aR, aZ, aNi);
    save_part(P, tid, aR, aZ, aNi);
  }

  const float C16 = 0.1f/6.f, C13 = 0.1f/3.f;
  for (int i=0;i<FWD_;i++){
    float cell[2][4], acc[2][4], tc[2][4], f;
    // eval1: half (P = knot i)
    gru_half(O4, P, tid, jg, bg, bcR,bcZ,bcI,bcH, y, cell);
    __syncthreads();
#pragma unroll
    for (int jj=0;jj<2;jj++){
#pragma unroll
      for (int bb=0;bb<4;bb++){
        f = (cell[jj][bb]-y[jj][bb])*10.f;
        acc[jj][bb] = y[jj][bb] + C16*f;  tc[jj][bb] = y[jj][bb] + 0.05f*f;
      }
      O4[(j0+jj)*4+bg] = make_float4(tc[jj][0],tc[jj][1],tc[jj][2],tc[jj][3]);
    }
    compute_x(g_umid + (size_t)i*B_*KIN_, O, jg, bg, b0, bev);
    __syncthreads();
    // eval2: full (captures P = mid)
    gru_full(O4, P, tid, jg, bg, bcR,bcZ,bcI,bcH, tc, cell);
    __syncthreads();
#pragma unroll
    for (int jj=0;jj<2;jj++){
#pragma unroll
      for (int bb=0;bb<4;bb++){
        f = (cell[jj][bb]-tc[jj][bb])*10.f;
        acc[jj][bb] += C13*f;  tc[jj][bb] = y[jj][bb] + 0.05f*f;
      }
      O4[(j0+jj)*4+bg] = make_float4(tc[jj][0],tc[jj][1],tc[jj][2],tc[jj][3]);
    }
    __syncthreads();
    // eval3: half (P = mid)
    gru_half(O4, P, tid, jg, bg, bcR,bcZ,bcI,bcH, tc, cell);
    __syncthreads();
#pragma unroll
    for (int jj=0;jj<2;jj++){
#pragma unroll
      for (int bb=0;bb<4;bb++){
        f = (cell[jj][bb]-tc[jj][bb])*10.f;
        acc[jj][bb] += C13*f;  tc[jj][bb] = y[jj][bb] + 0.1f*f;
      }
      O4[(j0+jj)*4+bg] = make_float4(tc[jj][0],tc[jj][1],tc[jj][2],tc[jj][3]);
    }
    compute_x(fwd_x + (size_t)i*B_*KIN_, O, jg, bg, b0, bev);
    __syncthreads();
    // eval4: full (captures P = knot i+1)
    gru_full(O4, P, tid, jg, bg, bcR,bcZ,bcI,bcH, tc, cell);
    __syncthreads();
#pragma unroll
    for (int jj=0;jj<2;jj++){
#pragma unroll
      for (int bb=0;bb<4;bb++){
        f = (cell[jj][bb]-tc[jj][bb])*10.f;
        y[jj][bb] = acc[jj][bb] + C16*f;
      }
      O4[(j0+jj)*4+bg] = make_float4(y[jj][0],y[jj][1],y[jj][2],y[jj][3]);
    }
    __syncthreads();
    // ---- head ----
    {
      u64 ha2[8] = {};
      for (int k=0;k<128;k++){
        u64 w2 = pk2(__ldg(g_W1T + k*256 + tid));
        const ulonglong2* orow = (const ulonglong2*)(O + k*16);
        ulonglong2 oa = orow[0], ob = orow[1];
        fma2(ha2[0], w2, oa.x); fma2(ha2[1], w2, oa.y);
        fma2(ha2[2], w2, ob.x); fma2(ha2[3], w2, ob.y);
        const ulonglong2* orow2 = orow + 2;
        ulonglong2 oc = orow2[0], od = orow2[1];
        fma2(ha2[4], w2, oc.x); fma2(ha2[5], w2, oc.y);
        fma2(ha2[6], w2, od.x); fma2(ha2[7], w2, od.y);
      }
      float4* Z4 = (float4*)Z;
#pragma unroll
      for (int q=0;q<4;q++){
        float a0,a1,a2,a3;
        upk2(a0,a1,ha2[q*2+0]); upk2(a2,a3,ha2[q*2+1]);
        Z4[tid*4+q] = make_float4(tanh_(a0),tanh_(a1),tanh_(a2),tanh_(a3));
      }
      __syncthreads();
      if (tid < 64){
        int c = tid>>4, b = tid&15;
        float s0=0.f,s1=0.f,s2=0.f,s3=0.f;
        for (int jp=0;jp<256;jp+=4){
          s0 = fmaf(__ldg(W2 + c*256 + jp+0), Z[(jp+0)*16+b], s0);
          s1 = fmaf(__ldg(W2 + c*256 + jp+1), Z[(jp+1)*16+b], s1);
          s2 = fmaf(__ldg(W2 + c*256 + jp+2), Z[(jp+2)*16+b], s2);
          s3 = fmaf(__ldg(W2 + c*256 + jp+3), Z[(jp+3)*16+b], s3);
        }
        out[((size_t)i*B_ + b0 + b)*KOUT_ + c] = (s0+s1)+(s2+s3);
      }
      __syncthreads();
    }
  }
}

extern "C" void kernel_launch(void* const* d_in, const int* in_sizes, int n_in,
                              void* d_out, int out_size){
  const float* pre_x = (const float*)d_in[0];
  const float* pre_y = (const float*)d_in[1];
  const float* fwd_x = (const float*)d_in[2];
  const float* W_ih  = (const float*)d_in[3];
  const float* W_hh  = (const float*)d_in[4];
  const float* b_ih  = (const float*)d_in[5];
  const float* b_hh  = (const float*)d_in[6];
  const float* W_e   = (const float*)d_in[7];
  const float* b_e   = (const float*)d_in[8];
  const float* Wc_ih = (const float*)d_in[9];
  const float* Wc_hh = (const float*)d_in[10];
  const float* bc_ih = (const float*)d_in[11];
  const float* bc_hh = (const float*)d_in[12];
  const float* W1    = (const float*)d_in[13];
  const float* W2    = (const float*)d_in[14];
  float* out = (float*)d_out;

  cudaFuncSetAttribute(ode_kernel, cudaFuncAttributeMaxDynamicSharedMemorySize, 57344);
  prep_all<<<512,256>>>(W_ih, W_hh, W_e, Wc_ih, Wc_hh, W1, pre_x, fwd_x);
  ode_kernel<<<NBLK_,256,57344>>>(pre_x, pre_y, fwd_x, b_ih, b_hh, b_e,
                                  bc_ih, bc_hh, W2, out);
}